// round 17
// baseline (speedup 1.0000x reference)
#include <cuda_runtime.h>
#include <cuda_fp16.h>
#include <cstdint>
#include <math.h>

#define B_    16
#define CIN   256
#define COUT  256
#define L_    4096
#define LP2   (L_ + 2)          // 2 leading zero rows (causal pad)
#define NR    5
#define KDIM  3840              // NR * 3 * CIN (halves)
#define BL    (B_ * L_)

// ---------------- scratch (device globals; allocation-free) ----------------
__device__ float  g_fr[NR * BL];                                 // fr[n][b*L+l]
__device__ __align__(16) __half g_Ah[COUT * KDIM];               // [o][(n*3+k)*256+c]
__device__ __align__(16) __half g_xth[(size_t)B_ * LP2 * CIN];   // [b][l+2][c] = half(x)

// ---------------- helpers ----------------
__device__ __forceinline__ void cp16(uint32_t dst, const void* src) {
    asm volatile("cp.async.cg.shared.global [%0], [%1], 16;" :: "r"(dst), "l"(src));
}
__device__ __forceinline__ void cp_commit() { asm volatile("cp.async.commit_group;"); }
__device__ __forceinline__ void ldsm4(uint32_t* r, uint32_t addr) {
    asm volatile("ldmatrix.sync.aligned.m8n8.x4.shared.b16 {%0,%1,%2,%3}, [%4];"
                 : "=r"(r[0]), "=r"(r[1]), "=r"(r[2]), "=r"(r[3]) : "r"(addr));
}
__device__ __forceinline__ void mma_f16(float* d, const uint32_t* a, uint32_t b0, uint32_t b1) {
    asm volatile("mma.sync.aligned.m16n8k16.row.col.f32.f16.f16.f32 "
                 "{%0,%1,%2,%3}, {%4,%5,%6,%7}, {%8,%9}, {%0,%1,%2,%3};"
                 : "+f"(d[0]), "+f"(d[1]), "+f"(d[2]), "+f"(d[3])
                 : "r"(a[0]), "r"(a[1]), "r"(a[2]), "r"(a[3]), "r"(b0), "r"(b1));
}

// ---------------------------------------------------------------------------
// FUSED prep v3 (512 threads): one pass over x produces
//   (a) g_xth transpose  (b) g_fr controller softmax  (c) its slice of g_Ah
// Controller processes 2 l's per thread (w-broadcast loads reused).
// grid (L/64, B) = 1024 blocks; prepA slice = 960 elems per block.
// ---------------------------------------------------------------------------
#define PREP_SW    (768 * NR)                    // 3840
#define PREP_XSST  68                            // xs row stride (floats)
#define PREP_XS    (128 * PREP_XSST)             // 8704
#define PREP_PART  (16 * 32 * NR * 2)            // 5120
#define PREP_SMEM  ((PREP_SW + PREP_XS + PREP_PART) * 4)
#define PREPA_TOT  (COUT * KDIM)                 // 983040 = 1024 * 960
#define PREPA_PER  960

__global__ void __launch_bounds__(512) prep_fused_kernel(
    const float* __restrict__ x, const float* __restrict__ cw,
    const float* __restrict__ cb, const float* __restrict__ wconv)
{
    extern __shared__ float psm[];
    float* sw   = psm;                     // [3840]
    float* xs   = sw + PREP_SW;            // [128][68]
    float* part = xs + PREP_XS;            // [cg16][lt2 32][n][2]

    const int tid = threadIdx.x;
    const int l0  = blockIdx.x * 64;
    const int b   = blockIdx.y;

    // (c) embedded prepA slice
    {
        const int base = (blockIdx.y * (int)gridDim.x + blockIdx.x) * PREPA_PER;
        for (int j = tid; j < PREPA_PER; j += 512) {
            const int i = base + j;
            const int o = i / KDIM;
            const int t = i - o * KDIM;
            const int n = t / 768;
            const int rem = t - n * 768;
            const int k = rem >> 8;
            const int c = rem & 255;
            g_Ah[i] = __float2half_rn(wconv[((n * COUT + o) * CIN + c) * 3 + k]);
        }
    }

    for (int i = tid; i < PREP_SW; i += 512) sw[i] = cw[i];

    const int lt2 = tid & 31;              // l pair: l = 2*lt2, 2*lt2+1
    const int cg  = tid >> 5;              // 0..15 : 8-channel subgroup
    float acc[NR][2];
#pragma unroll
    for (int n = 0; n < NR; n++) { acc[n][0] = 0.0f; acc[n][1] = 0.0f; }

#pragma unroll
    for (int cc = 0; cc < 2; cc++) {       // 2 rounds of 128 channels
        __syncthreads();                   // xs reusable (and sw ready, rnd 0)
        for (int i = tid; i < 128 * 66; i += 512) {
            const int c = i / 66, j = i - c * 66;
            const int gl = l0 - 2 + j;
            xs[c * PREP_XSST + j] = (gl >= 0)
                ? x[((size_t)(b * CIN + cc * 128 + c)) * L_ + gl] : 0.0f;
        }
        __syncthreads();

        // (a) transposed half writes
        for (int i = tid; i < 64 * 64; i += 512) {
            const int l = i >> 6, c2 = i & 63;
            __half2 h = __floats2half2_rn(xs[(2 * c2) * PREP_XSST + l + 2],
                                          xs[(2 * c2 + 1) * PREP_XSST + l + 2]);
            *reinterpret_cast<__half2*>(
                &g_xth[((size_t)b * LP2 + 2 + l0 + l) * CIN + cc * 128 + 2 * c2]) = h;
        }

        // (b) controller partials: 8 channels, 2 l's per thread
#pragma unroll
        for (int ci = 0; ci < 8; ci++) {
            const int c  = cg * 8 + ci;
            const int gc = cc * 128 + c;
            // x window for l=2*lt2 and l=2*lt2+1: xs[c][2lt2 .. 2lt2+3]
            const float2 u0 = *reinterpret_cast<const float2*>(
                &xs[c * PREP_XSST + 2 * lt2]);
            const float2 u1 = *reinterpret_cast<const float2*>(
                &xs[c * PREP_XSST + 2 * lt2 + 2]);
            const float xv0 = u0.x, xv1 = u0.y, xv2 = u1.x, xv3 = u1.y;
            const float* w0 = &sw[gc * 3 * NR];
#pragma unroll
            for (int n = 0; n < NR; n++) {
                const float wa = w0[n], wb = w0[NR + n], wcv = w0[2 * NR + n];
                acc[n][0] += xv0 * wa + xv1 * wb + xv2 * wcv;
                acc[n][1] += xv1 * wa + xv2 * wb + xv3 * wcv;
            }
        }
    }

#pragma unroll
    for (int n = 0; n < NR; n++) {
        part[((cg * 32 + lt2) * NR + n) * 2 + 0] = acc[n][0];
        part[((cg * 32 + lt2) * NR + n) * 2 + 1] = acc[n][1];
    }
    __syncthreads();

    // reduce + softmax (one thread per l)
    if (tid < 64) {
        const int l = tid;
        const int lp = l >> 1, hf = l & 1;
        float s[NR];
#pragma unroll
        for (int n = 0; n < NR; n++) {
            float t = __ldg(&cb[n]);
#pragma unroll
            for (int g = 0; g < 16; g++)
                t += part[((g * 32 + lp) * NR + n) * 2 + hf];
            s[n] = t;
        }
        float mx = s[0];
#pragma unroll
        for (int n = 1; n < NR; n++) mx = fmaxf(mx, s[n]);
        float e[NR], sum = 0.0f;
#pragma unroll
        for (int n = 0; n < NR; n++) { e[n] = __expf(s[n] - mx); sum += e[n]; }
        const float inv = 1.0f / sum;
        const size_t bl = (size_t)b * L_ + l0 + l;
#pragma unroll
        for (int n = 0; n < NR; n++) g_fr[(size_t)n * BL + bl] = e[n] * inv;
    }

    // zero the 2 causal-pad rows of g_xth (once, l0 == 0 blocks)
    if (blockIdx.x == 0 && tid < 256) {
        const int r = tid >> 7, c2 = tid & 127;
        *reinterpret_cast<__half2*>(
            &g_xth[((size_t)b * LP2 + r) * CIN + 2 * c2]) = __floats2half2_rn(0.f, 0.f);
    }
}

// ---------------------------------------------------------------------------
// fp16 GEMM (unchanged from Round 16): out(b, 128 o, 128 l), K = 3840.
// ---------------------------------------------------------------------------
#define BK     64
#define NTILE  60
#define A_BYT  (128 * 128)
#define B_BYT  (128 * 128)
#define STAGEB (A_BYT + B_BYT)
#define NST    3

__global__ void __launch_bounds__(256, 2) gemm_kernel(
    const float* __restrict__ bias,     // (NR, COUT)
    float* __restrict__ out)            // (B, COUT, L)
{
    extern __shared__ char smem[];
    const uint32_t sb = (uint32_t)__cvta_generic_to_shared(smem);
    float* sfr = reinterpret_cast<float*>(smem + NST * STAGEB);   // [NR][128]

    const int tid  = threadIdx.x;
    const int lane = tid & 31;
    const int wid  = tid >> 5;
    const int warp_m = wid >> 2;
    const int warp_n = wid & 3;

    const int b  = blockIdx.z;
    const int o0 = blockIdx.y * 128;
    const int l0 = blockIdx.x * 128;

    for (int i = tid; i < NR * 128; i += 256) {
        const int n = i >> 7, j = i & 127;
        sfr[i] = g_fr[(size_t)n * BL + (size_t)b * L_ + l0 + j];
    }

    const __half* Xt0 = g_xth + ((size_t)b * LP2 + l0) * CIN;

    const int ldrow = tid >> 3;
    const int ldc   = tid & 7;
    const uint32_t ldoff = (uint32_t)(ldrow * 128 + ((ldc ^ (ldrow & 7)) * 16));
    const size_t a_gstep = (size_t)32 * KDIM;
    const size_t b_gstep = (size_t)32 * CIN;

    auto load_tile = [&](int it, uint32_t sA) {
        const int n = it / 12;
        const int r = it - 12 * n;
        const int k = r >> 2;
        const int c0q = (r & 3) * 64;
        const __half* Ag = g_Ah + (size_t)o0 * KDIM + (size_t)it * BK
                         + (size_t)ldrow * KDIM + ldc * 8;
        const __half* Bg = Xt0 + (size_t)k * CIN + c0q
                         + (size_t)ldrow * CIN + ldc * 8;
        const uint32_t sB = sA + A_BYT;
#pragma unroll
        for (int i = 0; i < 4; i++) {
            cp16(sA + ldoff + (uint32_t)i * (32 * 128), Ag + (size_t)i * a_gstep);
            cp16(sB + ldoff + (uint32_t)i * (32 * 128), Bg + (size_t)i * b_gstep);
        }
        cp_commit();
    };

    float acc[4][4][4];
#pragma unroll
    for (int mt = 0; mt < 4; mt++)
#pragma unroll
        for (int ng = 0; ng < 4; ng++)
#pragma unroll
            for (int r = 0; r < 4; r++) acc[mt][ng][r] = 0.0f;

    load_tile(0, sb + 0 * STAGEB);
    load_tile(1, sb + 1 * STAGEB);

    const int acsel = lane >> 4;
    const int bcsel = (lane >> 3) & 1;
    const int frcol = warp_n * 32 + (lane >> 2);
    uint32_t aoff[4]; int r7a[4];
#pragma unroll
    for (int mt = 0; mt < 4; mt++) {
        const int row = warp_m * 64 + (lane & 15) + mt * 16;
        aoff[mt] = (uint32_t)(row * 128);
        r7a[mt]  = row & 7;
    }
    uint32_t boff[2]; int r7b[2];
#pragma unroll
    for (int g2 = 0; g2 < 2; g2++) {
        const int row = warp_n * 32 + (lane & 7) + ((lane >> 4) << 3) + g2 * 16;
        boff[g2] = (uint32_t)(row * 128);
        r7b[g2]  = row & 7;
    }

    __half2 frh[4];

#define GEMM_STEP(S, IT, RELOAD)                                              \
    do {                                                                      \
        asm volatile("cp.async.wait_group 1;");                               \
        __syncthreads();                                                      \
        if ((IT) + 2 < NTILE) load_tile((IT) + 2, sb + (((S) + 2) % NST) * STAGEB); \
        else cp_commit();                                                     \
        if (RELOAD) {                                                         \
            const int n_ = (IT) / 12;                                         \
            _Pragma("unroll")                                                 \
            for (int q = 0; q < 4; q++)                                       \
                frh[q] = __half2half2(__float2half_rn(sfr[n_ * 128 + frcol + q * 8])); \
        }                                                                     \
        const uint32_t sA_ = sb + (S) * STAGEB;                               \
        const uint32_t sB_ = sA_ + A_BYT;                                     \
        _Pragma("unroll")                                                     \
        for (int ks = 0; ks < 4; ks++) {                                      \
            uint32_t a_[4][4];                                                \
            _Pragma("unroll")                                                 \
            for (int mt = 0; mt < 4; mt++)                                    \
                ldsm4(a_[mt], sA_ + aoff[mt] +                                \
                      (uint32_t)(((ks * 2 + acsel) ^ r7a[mt]) * 16));         \
            uint32_t bb_[2][4];                                               \
            _Pragma("unroll")                                                 \
            for (int g2 = 0; g2 < 2; g2++)                                    \
                ldsm4(bb_[g2], sB_ + boff[g2] +                               \
                      (uint32_t)(((ks * 2 + bcsel) ^ r7b[g2]) * 16));         \
            _Pragma("unroll")                                                 \
            for (int g2 = 0; g2 < 2; g2++)                                    \
                _Pragma("unroll")                                             \
                for (int j = 0; j < 4; j++) {                                 \
                    __half2 v_ = *reinterpret_cast<__half2*>(&bb_[g2][j]);    \
                    v_ = __hmul2(v_, frh[2 * g2 + (j >> 1)]);                 \
                    bb_[g2][j] = *reinterpret_cast<uint32_t*>(&v_);           \
                }                                                             \
            _Pragma("unroll")                                                 \
            for (int mt = 0; mt < 4; mt++)                                    \
                _Pragma("unroll")                                             \
                for (int g2 = 0; g2 < 2; g2++) {                              \
                    mma_f16(acc[mt][2 * g2],     a_[mt], bb_[g2][0], bb_[g2][1]); \
                    mma_f16(acc[mt][2 * g2 + 1], a_[mt], bb_[g2][2], bb_[g2][3]); \
                }                                                             \
        }                                                                     \
    } while (0)

    for (int itb = 0; itb < NTILE; itb += 3) {
        const bool rb = (itb % 12) == 0;
        GEMM_STEP(0, itb + 0, rb);
        GEMM_STEP(1, itb + 1, false);
        GEMM_STEP(2, itb + 2, false);
    }
#undef GEMM_STEP

    // epilogue
    const int obase = o0 + warp_m * 64 + (lane >> 2);
    const int lloc0 = warp_n * 32 + (lane & 3) * 2;
    float* ob = out + ((size_t)b * COUT) * L_ + l0;

#pragma unroll
    for (int mt = 0; mt < 4; mt++) {
        const int o1 = obase + mt * 16;
        const int o2 = o1 + 8;
        float b1[NR], b2[NR];
#pragma unroll
        for (int n = 0; n < NR; n++) {
            b1[n] = __ldg(&bias[n * COUT + o1]);
            b2[n] = __ldg(&bias[n * COUT + o2]);
        }
#pragma unroll
        for (int ng = 0; ng < 4; ng++) {
            const int lloc = lloc0 + ng * 8;
            float t00 = 0.f, t01 = 0.f, t10 = 0.f, t11 = 0.f;
#pragma unroll
            for (int n = 0; n < NR; n++) {
                const float f0 = sfr[n * 128 + lloc];
                const float f1 = sfr[n * 128 + lloc + 1];
                t00 += f0 * b1[n]; t01 += f1 * b1[n];
                t10 += f0 * b2[n]; t11 += f1 * b2[n];
            }
            float2* p0 = reinterpret_cast<float2*>(ob + (size_t)o1 * L_ + lloc);
            float2* p1 = reinterpret_cast<float2*>(ob + (size_t)o2 * L_ + lloc);
            *p0 = make_float2(acc[mt][ng][0] + t00, acc[mt][ng][1] + t01);
            *p1 = make_float2(acc[mt][ng][2] + t10, acc[mt][ng][3] + t11);
        }
    }
}

#define GEMM_SMEM (NST * STAGEB + NR * 128 * 4)

// ---------------------------------------------------------------------------
// launch
// ---------------------------------------------------------------------------
extern "C" void kernel_launch(void* const* d_in, const int* in_sizes, int n_in,
                              void* d_out, int out_size) {
    const float* x  = (const float*)d_in[0];
    const float* bk = (const float*)d_in[1];
    const float* bb = (const float*)d_in[2];
    const float* cw = (const float*)d_in[3];
    const float* cb = (const float*)d_in[4];
    float* out = (float*)d_out;

    static int smem_set = 0;
    if (!smem_set) {
        cudaFuncSetAttribute(gemm_kernel, cudaFuncAttributeMaxDynamicSharedMemorySize,
                             GEMM_SMEM);
        cudaFuncSetAttribute(prep_fused_kernel, cudaFuncAttributeMaxDynamicSharedMemorySize,
                             PREP_SMEM);
        smem_set = 1;
    }

    prep_fused_kernel<<<dim3(L_ / 64, B_), 512, PREP_SMEM>>>(x, cw, cb, bk);
    gemm_kernel<<<dim3(L_ / 128, COUT / 128, B_), 256, GEMM_SMEM>>>(bb, out);
}